// round 15
// baseline (speedup 1.0000x reference)
#include <cuda_runtime.h>
#include <cuda_bf16.h>
#include <stdint.h>

#define NN 1024
#define EE 32
#define RSTRIDE 80                      // bf16 y row pitch in bytes (40 bf16)
#define MPITCH 1032                     // mask smem row pitch in ints (4128 B)

// Scratch (no allocations allowed)
__device__ float g_part[128];
__device__ unsigned int g_done = 0;

__device__ __forceinline__ void ldsm4(unsigned* r, unsigned addr) {
    asm volatile("ldmatrix.sync.aligned.m8n8.x4.shared.b16 {%0,%1,%2,%3}, [%4];"
        : "=r"(r[0]), "=r"(r[1]), "=r"(r[2]), "=r"(r[3]) : "r"(addr));
}
__device__ __forceinline__ void mma_bf16(float* d, const unsigned* a,
                                         const unsigned* bf, const float* c) {
    asm volatile("mma.sync.aligned.m16n8k16.row.col.f32.bf16.bf16.f32 "
        "{%0,%1,%2,%3}, {%4,%5,%6,%7}, {%8,%9}, {%10,%11,%12,%13};"
        : "=f"(d[0]), "=f"(d[1]), "=f"(d[2]), "=f"(d[3])
        : "r"(a[0]), "r"(a[1]), "r"(a[2]), "r"(a[3]),
          "r"(bf[0]), "r"(bf[1]),
          "f"(c[0]), "f"(c[1]), "f"(c[2]), "f"(c[3]));
}

// ---------------------------------------------------------------------------
// One launch. grid (32 i-tiles, 4 batches) x 512 threads, 1 CTA/SM (~217KB smem).
// Phase A: (1) thread 0 issues 32 x 4KB cp.async.bulk (TMA) for the CTA's
// 32x1024 int32 mask slice -> smem, mbarrier complete_tx; (2) y -> bf16 smem
// [1024][40] + norms, overlapped under the TMA stream; mbarrier wait.
// Phase B: mma.sync bf16 Gram; masks from smem (LDS only, zero DRAM in loop);
// epilogue 3 MUFU + Taylor-5 e^sim; additive row sums {T,A,P,C}.
// Phase C: analytic diag + closed form; deterministic 128-leaf tree.
// ---------------------------------------------------------------------------
__global__ void __launch_bounds__(512, 1)
fused_kernel(const float* __restrict__ emb,
             const float* __restrict__ coords,
             const int*   __restrict__ mask,
             float*       __restrict__ out) {
    extern __shared__ char smem[];
    char*   sBc  = smem;                                          // [1024][80B]
    float*  sN   = reinterpret_cast<float*>(smem + NN * RSTRIDE); // [1024]
    float4* sRow = reinterpret_cast<float4*>(sN + NN);            // [32][8]
    int*    sM   = reinterpret_cast<int*>(sRow + 32 * 8);         // [32][1032]
    __shared__ __align__(8) unsigned long long mbar;
    __shared__ int sIsLast;

    const int tid  = threadIdx.x;
    const int b    = blockIdx.y;
    const int i0   = blockIdx.x * 32;
    const int warp = tid >> 5;          // 0..15
    const int lane = tid & 31;
    const int g    = lane >> 2;         // 0..7
    const int tg   = lane & 3;          // 0..3
    const int rg   = warp >> 3;         // row-group 0/1
    const int q    = warp & 7;          // column eighth

    const unsigned sM_u32   = (unsigned)__cvta_generic_to_shared(sM);
    const unsigned mbar_u32 = (unsigned)__cvta_generic_to_shared(&mbar);

    // ---- Phase A1: TMA bulk copy of the mask slice (32 x 4KB, 1 thread) ----
    if (tid == 0) {
        asm volatile("mbarrier.init.shared.b64 [%0], 1;" :: "r"(mbar_u32) : "memory");
    }
    __syncthreads();   // mbar init visible before TMA targets it
    if (tid == 0) {
        asm volatile("mbarrier.arrive.expect_tx.shared.b64 _, [%0], %1;"
            :: "r"(mbar_u32), "r"(32 * NN * 4) : "memory");
        const int* mbase = mask + ((size_t)b * NN + i0) * NN;
#pragma unroll
        for (int r = 0; r < 32; r++) {
            asm volatile(
                "cp.async.bulk.shared::cta.global.mbarrier::complete_tx::bytes "
                "[%0], [%1], %2, [%3];"
                :: "r"(sM_u32 + (unsigned)(r * MPITCH * 4)),
                   "l"(mbase + (size_t)r * NN),
                   "r"(NN * 4), "r"(mbar_u32)
                : "memory");
        }
    }

    // ---- Phase A2: bf16 y + norms (2 rows/thread), under the TMA stream ----
#pragma unroll
    for (int k = 0; k < 2; k++) {
        const int j = tid + k * 512;
        const float* ep = emb + ((size_t)(b * NN + j)) * EE;
        float v[EE];
#pragma unroll
        for (int e = 0; e < EE; e += 4) {
            float4 t = *reinterpret_cast<const float4*>(ep + e);
            v[e] = t.x; v[e + 1] = t.y; v[e + 2] = t.z; v[e + 3] = t.w;
        }
        float2 c2 = *reinterpret_cast<const float2*>(coords + ((size_t)(b * NN + j)) * 2);
        v[0] += c2.x; v[1] += c2.y;
        unsigned w[16];
        float n = 0.f;
#pragma unroll
        for (int p = 0; p < 16; p++) {
            __nv_bfloat162 h2 = __floats2bfloat162_rn(v[2 * p], v[2 * p + 1]);
            w[p] = *reinterpret_cast<unsigned*>(&h2);
            float lo = __bfloat162float(__low2bfloat16(h2));
            float hi = __bfloat162float(__high2bfloat16(h2));
            n = fmaf(lo, lo, n);
            n = fmaf(hi, hi, n);
        }
        uint4* row = reinterpret_cast<uint4*>(sBc + (size_t)j * RSTRIDE);
        row[0] = make_uint4(w[0], w[1], w[2], w[3]);
        row[1] = make_uint4(w[4], w[5], w[6], w[7]);
        row[2] = make_uint4(w[8], w[9], w[10], w[11]);
        row[3] = make_uint4(w[12], w[13], w[14], w[15]);
        sN[j] = n;
    }
    __syncthreads();   // sB/sN stores visible

    // wait for TMA completion (acquire orders subsequent LDS reads of sM)
    {
        unsigned done;
        asm volatile(
            "{\n\t.reg .pred p;\n\t"
            "mbarrier.try_wait.parity.acquire.cta.shared::cta.b64 p, [%1], 0;\n\t"
            "selp.b32 %0, 1, 0, p;\n\t}"
            : "=r"(done) : "r"(mbar_u32) : "memory");
        if (!done) {
            asm volatile(
                "{\n\t.reg .pred P1;\n\t"
                "WAIT_LOOP_%=:\n\t"
                "mbarrier.try_wait.parity.acquire.cta.shared::cta.b64 P1, [%0], 0, 0x989680;\n\t"
                "@P1 bra.uni WAIT_DONE_%=;\n\t"
                "bra.uni WAIT_LOOP_%=;\n\t"
                "WAIT_DONE_%=:\n\t}"
                :: "r"(mbar_u32) : "memory");
        }
    }

    // ---------------- Phase B: mma Gram + smem mask + epilogue --------------
    const unsigned sB_u32 = (unsigned)__cvta_generic_to_shared(sBc);

    // A fragments (rows i0 + rg*16 .. +15), k-lo and k-hi, held in registers
    unsigned aLo[4], aHi[4];
    {
        const int m = lane >> 3;                    // matrix index 0..3
        const int rowA = i0 + rg * 16 + ((m & 1) << 3) + (lane & 7);
        const unsigned colb = (unsigned)((m >> 1) << 4);
        unsigned addr = sB_u32 + (unsigned)rowA * RSTRIDE + colb;
        ldsm4(aLo, addr);
        ldsm4(aHi, addr + 32);
    }

    const int rL = rg * 16 + g;         // local row (lo)
    const int rH = rL + 8;              // local row (hi)
    const float ni_lo = sN[i0 + rL];
    const float ni_hi = sN[i0 + rH];
    unsigned mAL = sM_u32 + (unsigned)((rL * MPITCH + q * 128 + 2 * tg) * 4);
    unsigned mAH = sM_u32 + (unsigned)((rH * MPITCH + q * 128 + 2 * tg) * 4);

    float T0 = 0.f, A0 = 0.f, P0 = 0.f, T1 = 0.f, A1 = 0.f, P1 = 0.f;
    int   C0 = 0, C1 = 0;

    const float L2E  = 1.44269504f;
    const float N5L2 = -7.21347520f;    // -5*log2(e)

    unsigned bf[4];
    ldsm4(bf, sB_u32 + (unsigned)(q * 128 + (lane & 7)) * RSTRIDE
               + (unsigned)((lane >> 3) << 4));

#pragma unroll 1
    for (int t = 0; t < 16; t++) {
        // B fragment for next tile (smem)
        unsigned bfN[4];
        {
            const int tn = (t < 15) ? t + 1 : 15;
            unsigned an = sB_u32 + (unsigned)(q * 128 + tn * 8 + (lane & 7)) * RSTRIDE
                        + (unsigned)((lane >> 3) << 4);
            ldsm4(bfN, an);
        }

        // Gram for this 16x8 tile
        float d[4];
        const float z[4] = {0.f, 0.f, 0.f, 0.f};
        mma_bf16(d, aLo, &bf[0], z);
        mma_bf16(d, aHi, &bf[2], d);

        // masks from smem (LDS.64, conflict-free with MPITCH=1032)
        int2 cL, cH;
        asm volatile("ld.shared.v2.u32 {%0,%1}, [%2];"
            : "=r"(cL.x), "=r"(cL.y) : "r"(mAL + (unsigned)(t * 32)));
        asm volatile("ld.shared.v2.u32 {%0,%1}, [%2];"
            : "=r"(cH.x), "=r"(cH.y) : "r"(mAH + (unsigned)(t * 32)));

        const int j0 = q * 128 + t * 8;
        float2 njp = *reinterpret_cast<const float2*>(sN + j0 + 2 * tg);

        float ninj[4] = {ni_lo + njp.x, ni_lo + njp.y, ni_hi + njp.x, ni_hi + njp.y};
        int   mi[4]   = {cL.x, cL.y, cH.x, cH.y};
#pragma unroll
        for (int c = 0; c < 4; c++) {
            float ssq  = fmaxf(fmaf(-2.f, d[c], ninj[c]), 0.f);
            float dist = ssq * rsqrtf(fmaxf(ssq, 1e-37f));        // MUFU
            float u    = exp2f(fmaf(dist, L2E, N5L2));            // MUFU
            float sim  = __fdividef(1.f, 1.f + u);                // MUFU
            // e^sim via degree-5 Taylor (sim in (0,1))
            float e = fmaf(sim, 8.3333333e-3f, 4.1666667e-2f);
            e = fmaf(sim, e, 0.16666667f);
            e = fmaf(sim, e, 0.5f);
            e = fmaf(sim, e, 1.f);
            e = fmaf(sim, e, 1.f);
            float mf = (float)mi[c];
            if (c < 2) { T0 += e; A0 = fmaf(mf, e, A0); P0 = fmaf(mf, sim, P0); C0 += mi[c]; }
            else       { T1 += e; A1 = fmaf(mf, e, A1); P1 = fmaf(mf, sim, P1); C1 += mi[c]; }
        }

        bf[0] = bfN[0]; bf[1] = bfN[1]; bf[2] = bfN[2]; bf[3] = bfN[3];
    }

    // reduce across the 4 lanes (tg) sharing each row
    float c0f = (float)C0, c1f = (float)C1;
#pragma unroll
    for (int o = 2; o > 0; o >>= 1) {
        T0 += __shfl_down_sync(0xffffffffu, T0, o, 4);
        A0 += __shfl_down_sync(0xffffffffu, A0, o, 4);
        P0 += __shfl_down_sync(0xffffffffu, P0, o, 4);
        c0f += __shfl_down_sync(0xffffffffu, c0f, o, 4);
        T1 += __shfl_down_sync(0xffffffffu, T1, o, 4);
        A1 += __shfl_down_sync(0xffffffffu, A1, o, 4);
        P1 += __shfl_down_sync(0xffffffffu, P1, o, 4);
        c1f += __shfl_down_sync(0xffffffffu, c1f, o, 4);
    }
    if (tg == 0) {
        sRow[(size_t)rL * 8 + q] = make_float4(T0, A0, P0, c0f);
        sRow[(size_t)rH * 8 + q] = make_float4(T1, A1, P1, c1f);
    }
    __syncthreads();

    // ---------------- Phase C: per-row closed form (warp 0) -----------------
    if (tid < 32) {
        const int row = tid;
        float4 s = make_float4(0.f, 0.f, 0.f, 0.f);
#pragma unroll
        for (int qq = 0; qq < 8; qq++) {
            float4 v = sRow[(size_t)row * 8 + qq];
            s.x += v.x; s.y += v.y; s.z += v.z; s.w += v.w;
        }
        const float EXDIAG_T = 2.69860f;    // Taylor-5 of e^{sigmoid(5)}
        float md = (sM[row * MPITCH + (i0 + row)] != 0) ? 1.f : 0.f;
        float S  = s.x - s.y - (1.f - md) * EXDIAG_T;
        float L  = __logf(S);
        float contrib = s.w * L - s.z + s.y * __fdividef(1.f, S);
#pragma unroll
        for (int o = 16; o > 0; o >>= 1)
            contrib += __shfl_down_sync(0xffffffffu, contrib, o);
        if (tid == 0) {
            g_part[b * 32 + blockIdx.x] = contrib;
            __threadfence();
            unsigned v = atomicAdd(&g_done, 1u);
            sIsLast = (v == 127u);
        }
    }
    __syncthreads();

    // Last CTA: deterministic fixed-order tree over the 128 partials
    if (sIsLast) {
        double* dsh = reinterpret_cast<double*>(smem);
        if (tid < 128) dsh[tid] = (double)g_part[tid];
        __syncthreads();
#pragma unroll
        for (int s = 64; s > 0; s >>= 1) {
            if (tid < s) dsh[tid] += dsh[tid + s];
            __syncthreads();
        }
        if (tid == 0) {
            out[0] = (float)dsh[0];
            g_done = 0;                 // reset for next replay
        }
    }
}

// ---------------------------------------------------------------------------
extern "C" void kernel_launch(void* const* d_in, const int* in_sizes, int n_in,
                              void* d_out, int out_size) {
    (void)in_sizes; (void)n_in; (void)out_size;
    const float* emb    = (const float*)d_in[0];   // [4,1024,32]
    const float* coords = (const float*)d_in[1];   // [4,1024,2]
    const int*   mask   = (const int*)d_in[2];     // [4,1024,1024] bool->int32
    float* out          = (float*)d_out;           // scalar

    size_t smem = (size_t)NN * RSTRIDE              // sB      81920
                + (size_t)NN * sizeof(float)        // sN       4096
                + (size_t)32 * 8 * sizeof(float4)   // sRow     4096
                + (size_t)32 * MPITCH * sizeof(int);// sM     132096
    cudaFuncSetAttribute(fused_kernel, cudaFuncAttributeMaxDynamicSharedMemorySize,
                         (int)smem);
    fused_kernel<<<dim3(32, 4), 512, smem>>>(emb, coords, mask, out);
}

// round 16
// speedup vs baseline: 1.0305x; 1.0305x over previous
#include <cuda_runtime.h>
#include <cuda_bf16.h>
#include <stdint.h>

#define NN 1024
#define EE 32
#define RSTRIDE 80                      // bf16 y row pitch in bytes (40 bf16)

// Scratch (no allocations allowed)
__device__ float g_part[128];
__device__ unsigned int g_done = 0;

__device__ __forceinline__ void ldsm4(unsigned* r, unsigned addr) {
    asm volatile("ldmatrix.sync.aligned.m8n8.x4.shared.b16 {%0,%1,%2,%3}, [%4];"
        : "=r"(r[0]), "=r"(r[1]), "=r"(r[2]), "=r"(r[3]) : "r"(addr));
}
__device__ __forceinline__ void mma_bf16(float* d, const unsigned* a,
                                         const unsigned* bf, const float* c) {
    asm volatile("mma.sync.aligned.m16n8k16.row.col.f32.bf16.bf16.f32 "
        "{%0,%1,%2,%3}, {%4,%5,%6,%7}, {%8,%9}, {%10,%11,%12,%13};"
        : "=f"(d[0]), "=f"(d[1]), "=f"(d[2]), "=f"(d[3])
        : "r"(a[0]), "r"(a[1]), "r"(a[2]), "r"(a[3]),
          "r"(bf[0]), "r"(bf[1]),
          "f"(c[0]), "f"(c[1]), "f"(c[2]), "f"(c[3]));
}

// ---------------------------------------------------------------------------
// One launch. grid (32 i-tiles, 4 batches) x 1024 threads, 1 CTA/SM (~92KB smem,
// occ 50%). 32 warps: rg = warp&1 (16-row group), q = warp>>1 (64-col sixteenth),
// 8 tiles of 16x8 per warp. Gram via mma.sync bf16; masks via direct LDG with
// 1-tile prefetch (8 warps/SMSP hide the latency). Epilogue: 3 MUFU
// (sqrt.approx, ex2, rcp) + Taylor-5 e^sim. Additive row sums {T,A,P,C};
// analytic diag; deterministic 128-leaf final tree.
// ---------------------------------------------------------------------------
__global__ void __launch_bounds__(1024, 1)
fused_kernel(const float* __restrict__ emb,
             const float* __restrict__ coords,
             const int*   __restrict__ mask,
             float*       __restrict__ out) {
    extern __shared__ char smem[];
    char*   sBc  = smem;                                          // [1024][80B]
    float*  sN   = reinterpret_cast<float*>(smem + NN * RSTRIDE); // [1024]
    float4* sRow = reinterpret_cast<float4*>(sN + NN);            // [32][16]
    __shared__ int sIsLast;

    const int tid  = threadIdx.x;
    const int b    = blockIdx.y;
    const int i0   = blockIdx.x * 32;
    const int warp = tid >> 5;          // 0..31
    const int lane = tid & 31;
    const int g    = lane >> 2;         // 0..7
    const int tg   = lane & 3;          // 0..3
    const int rg   = warp & 1;          // 16-row group 0/1
    const int q    = warp >> 1;         // 0..15 column sixteenth (64 cols)

    // ---------------- Phase A: bf16 y + norms (1 row/thread, low regs) ------
    {
        const int j = tid;
        const float* ep = emb + ((size_t)(b * NN + j)) * EE;
        float2 c2 = *reinterpret_cast<const float2*>(coords + ((size_t)(b * NN + j)) * 2);
        uint4* row = reinterpret_cast<uint4*>(sBc + (size_t)j * RSTRIDE);
        float n = 0.f;
#pragma unroll
        for (int e = 0; e < EE; e += 8) {
            float4 t0 = *reinterpret_cast<const float4*>(ep + e);
            float4 t1 = *reinterpret_cast<const float4*>(ep + e + 4);
            if (e == 0) { t0.x += c2.x; t0.y += c2.y; }
            __nv_bfloat162 h0 = __floats2bfloat162_rn(t0.x, t0.y);
            __nv_bfloat162 h1 = __floats2bfloat162_rn(t0.z, t0.w);
            __nv_bfloat162 h2 = __floats2bfloat162_rn(t1.x, t1.y);
            __nv_bfloat162 h3 = __floats2bfloat162_rn(t1.z, t1.w);
            uint4 wv;
            wv.x = *reinterpret_cast<unsigned*>(&h0);
            wv.y = *reinterpret_cast<unsigned*>(&h1);
            wv.z = *reinterpret_cast<unsigned*>(&h2);
            wv.w = *reinterpret_cast<unsigned*>(&h3);
            row[e >> 3] = wv;
            float f;
            f = __bfloat162float(__low2bfloat16(h0));  n = fmaf(f, f, n);
            f = __bfloat162float(__high2bfloat16(h0)); n = fmaf(f, f, n);
            f = __bfloat162float(__low2bfloat16(h1));  n = fmaf(f, f, n);
            f = __bfloat162float(__high2bfloat16(h1)); n = fmaf(f, f, n);
            f = __bfloat162float(__low2bfloat16(h2));  n = fmaf(f, f, n);
            f = __bfloat162float(__high2bfloat16(h2)); n = fmaf(f, f, n);
            f = __bfloat162float(__low2bfloat16(h3));  n = fmaf(f, f, n);
            f = __bfloat162float(__high2bfloat16(h3)); n = fmaf(f, f, n);
        }
        sN[j] = n;
    }
    __syncthreads();

    // ---------------- Phase B: mma Gram + LDG mask + epilogue ---------------
    const unsigned sB_u32 = (unsigned)__cvta_generic_to_shared(sBc);

    // A fragments (rows i0 + rg*16 .. +15), k-lo and k-hi
    unsigned aLo[4], aHi[4];
    {
        const int m = lane >> 3;                    // matrix index 0..3
        const int rowA = i0 + rg * 16 + ((m & 1) << 3) + (lane & 7);
        unsigned addr = sB_u32 + (unsigned)rowA * RSTRIDE
                      + (unsigned)((m >> 1) << 4);
        ldsm4(aLo, addr);
        ldsm4(aHi, addr + 32);
    }

    const int rL = rg * 16 + g;         // local row (lo)
    const int rH = rL + 8;              // local row (hi)
    const float ni_lo = sN[i0 + rL];
    const float ni_hi = sN[i0 + rH];
    const int* pL = mask + ((size_t)(b * NN + i0 + rL)) * NN + q * 64 + 2 * tg;
    const int* pH = mask + ((size_t)(b * NN + i0 + rH)) * NN + q * 64 + 2 * tg;

    float T0 = 0.f, A0 = 0.f, P0 = 0.f, T1 = 0.f, A1 = 0.f, P1 = 0.f;
    int   C0 = 0, C1 = 0;

    const float L2E  = 1.44269504f;
    const float N5L2 = -7.21347520f;    // -5*log2(e)

    // 1-deep prefetch: B fragment + masks for tile 0
    unsigned bf[4];
    ldsm4(bf, sB_u32 + (unsigned)(q * 64 + (lane & 7)) * RSTRIDE
               + (unsigned)((lane >> 3) << 4));
    int2 mL = *reinterpret_cast<const int2*>(pL);
    int2 mH = *reinterpret_cast<const int2*>(pH);

#pragma unroll 1
    for (int t = 0; t < 8; t++) {
        // prefetch next tile (clamped)
        const int tn = (t < 7) ? t + 1 : 7;
        unsigned bfN[4];
        ldsm4(bfN, sB_u32 + (unsigned)(q * 64 + tn * 8 + (lane & 7)) * RSTRIDE
                   + (unsigned)((lane >> 3) << 4));
        int2 mLn = *reinterpret_cast<const int2*>(pL + tn * 8);
        int2 mHn = *reinterpret_cast<const int2*>(pH + tn * 8);

        // Gram for this 16x8 tile
        float d[4];
        const float z[4] = {0.f, 0.f, 0.f, 0.f};
        mma_bf16(d, aLo, &bf[0], z);
        mma_bf16(d, aHi, &bf[2], d);

        const int j0 = q * 64 + t * 8;
        float2 njp = *reinterpret_cast<const float2*>(sN + j0 + 2 * tg);

        float ninj[4] = {ni_lo + njp.x, ni_lo + njp.y, ni_hi + njp.x, ni_hi + njp.y};
        int   mi[4]   = {mL.x, mL.y, mH.x, mH.y};
#pragma unroll
        for (int c = 0; c < 4; c++) {
            float ssq  = fmaxf(fmaf(-2.f, d[c], ninj[c]), 0.f);
            float dist;
            asm("sqrt.approx.f32 %0, %1;" : "=f"(dist) : "f"(ssq));   // MUFU
            float u    = exp2f(fmaf(dist, L2E, N5L2));                // MUFU
            float sim  = __fdividef(1.f, 1.f + u);                    // MUFU
            // e^sim via degree-5 Taylor (sim in (0,1))
            float e = fmaf(sim, 8.3333333e-3f, 4.1666667e-2f);
            e = fmaf(sim, e, 0.16666667f);
            e = fmaf(sim, e, 0.5f);
            e = fmaf(sim, e, 1.f);
            e = fmaf(sim, e, 1.f);
            float mf = (float)mi[c];
            if (c < 2) { T0 += e; A0 = fmaf(mf, e, A0); P0 = fmaf(mf, sim, P0); C0 += mi[c]; }
            else       { T1 += e; A1 = fmaf(mf, e, A1); P1 = fmaf(mf, sim, P1); C1 += mi[c]; }
        }

        bf[0] = bfN[0]; bf[1] = bfN[1]; bf[2] = bfN[2]; bf[3] = bfN[3];
        mL = mLn; mH = mHn;
    }

    // reduce across the 4 lanes (tg) sharing each row
    float c0f = (float)C0, c1f = (float)C1;
#pragma unroll
    for (int o = 2; o > 0; o >>= 1) {
        T0 += __shfl_down_sync(0xffffffffu, T0, o, 4);
        A0 += __shfl_down_sync(0xffffffffu, A0, o, 4);
        P0 += __shfl_down_sync(0xffffffffu, P0, o, 4);
        c0f += __shfl_down_sync(0xffffffffu, c0f, o, 4);
        T1 += __shfl_down_sync(0xffffffffu, T1, o, 4);
        A1 += __shfl_down_sync(0xffffffffu, A1, o, 4);
        P1 += __shfl_down_sync(0xffffffffu, P1, o, 4);
        c1f += __shfl_down_sync(0xffffffffu, c1f, o, 4);
    }
    if (tg == 0) {
        sRow[(size_t)rL * 16 + q] = make_float4(T0, A0, P0, c0f);
        sRow[(size_t)rH * 16 + q] = make_float4(T1, A1, P1, c1f);
    }
    __syncthreads();

    // ---------------- Phase C: per-row closed form (warp 0) -----------------
    if (tid < 32) {
        const int row = tid;
        const int i   = i0 + row;
        float4 s = make_float4(0.f, 0.f, 0.f, 0.f);
#pragma unroll
        for (int qq = 0; qq < 16; qq++) {
            float4 v = sRow[(size_t)row * 16 + qq];
            s.x += v.x; s.y += v.y; s.z += v.z; s.w += v.w;
        }
        const float EXDIAG_T = 2.69860f;    // Taylor-5 of e^{sigmoid(5)}
        float md = (mask[((size_t)(b * NN + i)) * NN + i] != 0) ? 1.f : 0.f;
        float S  = s.x - s.y - (1.f - md) * EXDIAG_T;
        float L  = __logf(S);
        float contrib = s.w * L - s.z + s.y * __fdividef(1.f, S);
#pragma unroll
        for (int o = 16; o > 0; o >>= 1)
            contrib += __shfl_down_sync(0xffffffffu, contrib, o);
        if (tid == 0) {
            g_part[b * 32 + blockIdx.x] = contrib;
            __threadfence();
            unsigned v = atomicAdd(&g_done, 1u);
            sIsLast = (v == 127u);
        }
    }
    __syncthreads();

    // Last CTA: deterministic fixed-order tree over the 128 partials
    if (sIsLast) {
        double* dsh = reinterpret_cast<double*>(smem);
        if (tid < 128) dsh[tid] = (double)g_part[tid];
        __syncthreads();
#pragma unroll
        for (int s = 64; s > 0; s >>= 1) {
            if (tid < s) dsh[tid] += dsh[tid + s];
            __syncthreads();
        }
        if (tid == 0) {
            out[0] = (float)dsh[0];
            g_done = 0;                 // reset for next replay
        }
    }
}

// ---------------------------------------------------------------------------
extern "C" void kernel_launch(void* const* d_in, const int* in_sizes, int n_in,
                              void* d_out, int out_size) {
    (void)in_sizes; (void)n_in; (void)out_size;
    const float* emb    = (const float*)d_in[0];   // [4,1024,32]
    const float* coords = (const float*)d_in[1];   // [4,1024,2]
    const int*   mask   = (const int*)d_in[2];     // [4,1024,1024] bool->int32
    float* out          = (float*)d_out;           // scalar

    size_t smem = (size_t)NN * RSTRIDE              // sB    81920
                + (size_t)NN * sizeof(float)        // sN     4096
                + (size_t)32 * 16 * sizeof(float4); // sRow   8192
    cudaFuncSetAttribute(fused_kernel, cudaFuncAttributeMaxDynamicSharedMemorySize,
                         (int)smem);
    fused_kernel<<<dim3(32, 4), 1024, smem>>>(emb, coords, mask, out);
}

// round 17
// speedup vs baseline: 1.0530x; 1.0218x over previous
#include <cuda_runtime.h>
#include <cuda_bf16.h>
#include <stdint.h>

#define NN 1024
#define EE 32
#define RSTRIDE 80                      // bf16 y row pitch in bytes (40 bf16)

// Scratch (no allocations allowed)
__device__ float g_part[128];
__device__ unsigned int g_done = 0;

__device__ __forceinline__ void ldsm4(unsigned* r, unsigned addr) {
    asm volatile("ldmatrix.sync.aligned.m8n8.x4.shared.b16 {%0,%1,%2,%3}, [%4];"
        : "=r"(r[0]), "=r"(r[1]), "=r"(r[2]), "=r"(r[3]) : "r"(addr));
}
__device__ __forceinline__ void mma_bf16(float* d, const unsigned* a,
                                         const unsigned* bf, const float* c) {
    asm volatile("mma.sync.aligned.m16n8k16.row.col.f32.bf16.bf16.f32 "
        "{%0,%1,%2,%3}, {%4,%5,%6,%7}, {%8,%9}, {%10,%11,%12,%13};"
        : "=f"(d[0]), "=f"(d[1]), "=f"(d[2]), "=f"(d[3])
        : "r"(a[0]), "r"(a[1]), "r"(a[2]), "r"(a[3]),
          "r"(bf[0]), "r"(bf[1]),
          "f"(c[0]), "f"(c[1]), "f"(c[2]), "f"(c[3]));
}

// ---------------------------------------------------------------------------
// One launch. grid (32 i-tiles, 4 batches) x 512 threads, 1 CTA/SM (~91KB smem).
// R11 structure (best measured: 18.9us), epilogue slimmed to pure MUFU+FMA:
// sqrt.approx -> ex2.approx -> rcp.approx, e^sim by Taylor-3. Dead LDSM removed.
// Masks via direct LDG, 1-tile prefetch. Additive row sums {T,A,P,C};
// analytic diag (Taylor-3-consistent constant); deterministic 128-leaf tree.
// ---------------------------------------------------------------------------
__global__ void __launch_bounds__(512, 1)
fused_kernel(const float* __restrict__ emb,
             const float* __restrict__ coords,
             const int*   __restrict__ mask,
             float*       __restrict__ out) {
    extern __shared__ char smem[];
    char*   sBc  = smem;                                          // [1024][80B]
    float*  sN   = reinterpret_cast<float*>(smem + NN * RSTRIDE); // [1024]
    float4* sRow = reinterpret_cast<float4*>(sN + NN);            // [32][8]
    __shared__ int sIsLast;

    const int tid  = threadIdx.x;
    const int b    = blockIdx.y;
    const int i0   = blockIdx.x * 32;
    const int warp = tid >> 5;          // 0..15
    const int lane = tid & 31;
    const int g    = lane >> 2;         // 0..7
    const int tg   = lane & 3;          // 0..3
    const int rg   = warp >> 3;         // row-group 0/1
    const int q    = warp & 7;          // column eighth

    // ---------------- Phase A: bf16 y + norms (2 rows/thread) ---------------
#pragma unroll
    for (int k = 0; k < 2; k++) {
        const int j = tid + k * 512;
        const float* ep = emb + ((size_t)(b * NN + j)) * EE;
        float v[EE];
#pragma unroll
        for (int e = 0; e < EE; e += 4) {
            float4 t = *reinterpret_cast<const float4*>(ep + e);
            v[e] = t.x; v[e + 1] = t.y; v[e + 2] = t.z; v[e + 3] = t.w;
        }
        float2 c2 = *reinterpret_cast<const float2*>(coords + ((size_t)(b * NN + j)) * 2);
        v[0] += c2.x; v[1] += c2.y;
        unsigned w[16];
        float n = 0.f;
#pragma unroll
        for (int p = 0; p < 16; p++) {
            __nv_bfloat162 h2 = __floats2bfloat162_rn(v[2 * p], v[2 * p + 1]);
            w[p] = *reinterpret_cast<unsigned*>(&h2);
            float lo = __bfloat162float(__low2bfloat16(h2));
            float hi = __bfloat162float(__high2bfloat16(h2));
            n = fmaf(lo, lo, n);
            n = fmaf(hi, hi, n);
        }
        uint4* row = reinterpret_cast<uint4*>(sBc + (size_t)j * RSTRIDE);
        row[0] = make_uint4(w[0], w[1], w[2], w[3]);
        row[1] = make_uint4(w[4], w[5], w[6], w[7]);
        row[2] = make_uint4(w[8], w[9], w[10], w[11]);
        row[3] = make_uint4(w[12], w[13], w[14], w[15]);
        sN[j] = n;
    }
    __syncthreads();

    // ---------------- Phase B: mma Gram + LDG mask + slim epilogue ----------
    const unsigned sB_u32 = (unsigned)__cvta_generic_to_shared(sBc);

    // A fragments (rows i0 + rg*16 .. +15), k-lo and k-hi, held in registers
    unsigned aLo[4], aHi[4];
    {
        const int m = lane >> 3;                    // matrix index 0..3
        const int rowA = i0 + rg * 16 + ((m & 1) << 3) + (lane & 7);
        const unsigned colb = (unsigned)((m >> 1) << 4);
        unsigned addr = sB_u32 + (unsigned)rowA * RSTRIDE + colb;
        ldsm4(aLo, addr);
        ldsm4(aHi, addr + 32);
    }

    const int i_lo = i0 + rg * 16 + g;
    const int i_hi = i_lo + 8;
    const float ni_lo = sN[i_lo];
    const float ni_hi = sN[i_hi];
    const int* pL = mask + ((size_t)(b * NN + i_lo)) * NN + q * 128 + 2 * tg;
    const int* pH = mask + ((size_t)(b * NN + i_hi)) * NN + q * 128 + 2 * tg;

    float T0 = 0.f, A0 = 0.f, P0 = 0.f, T1 = 0.f, A1 = 0.f, P1 = 0.f;
    int   C0 = 0, C1 = 0;

    const float L2E  = 1.44269504f;
    const float N5L2 = -7.21347520f;    // -5*log2(e)

    const unsigned baddr = sB_u32 + (unsigned)(q * 128 + (lane & 7)) * RSTRIDE
                         + (unsigned)((lane >> 3) << 4);
    unsigned bf[4];
    ldsm4(bf, baddr);
    int2 mLo = *reinterpret_cast<const int2*>(pL);
    int2 mHi = *reinterpret_cast<const int2*>(pH);

#pragma unroll 1
    for (int t = 0; t < 16; t++) {
        // prefetch next tile (clamped; single clean LDSM)
        const int tn = (t < 15) ? t + 1 : 15;
        unsigned bfN[4];
        ldsm4(bfN, baddr + (unsigned)tn * 640u);
        int2 mLoN = *reinterpret_cast<const int2*>(pL + tn * 8);
        int2 mHiN = *reinterpret_cast<const int2*>(pH + tn * 8);

        // Gram for this 16x8 tile
        float d[4];
        const float z[4] = {0.f, 0.f, 0.f, 0.f};
        mma_bf16(d, aLo, &bf[0], z);
        mma_bf16(d, aHi, &bf[2], d);

        const int j0 = q * 128 + t * 8;
        float2 njp = *reinterpret_cast<const float2*>(sN + j0 + 2 * tg);

        float ninj[4] = {ni_lo + njp.x, ni_lo + njp.y, ni_hi + njp.x, ni_hi + njp.y};
        int   mi[4]   = {mLo.x, mLo.y, mHi.x, mHi.y};
#pragma unroll
        for (int c = 0; c < 4; c++) {
            float ssq  = fmaxf(fmaf(-2.f, d[c], ninj[c]), 0.f);
            float dist, u, w;
            asm("sqrt.approx.f32 %0, %1;" : "=f"(dist) : "f"(ssq));     // MUFU
            float l = fmaf(dist, L2E, N5L2);
            asm("ex2.approx.f32 %0, %1;" : "=f"(u) : "f"(l));           // MUFU
            asm("rcp.approx.f32 %0, %1;" : "=f"(w) : "f"(1.f + u));     // MUFU
            // e^sim via Taylor-3 (sim = w in (0,1))
            float e = fmaf(w, 0.16666667f, 0.5f);
            e = fmaf(w, e, 1.f);
            e = fmaf(w, e, 1.f);
            float mf = (float)mi[c];
            if (c < 2) { T0 += e; A0 = fmaf(mf, e, A0); P0 = fmaf(mf, w, P0); C0 += mi[c]; }
            else       { T1 += e; A1 = fmaf(mf, e, A1); P1 = fmaf(mf, w, P1); C1 += mi[c]; }
        }

        bf[0] = bfN[0]; bf[1] = bfN[1]; bf[2] = bfN[2]; bf[3] = bfN[3];
        mLo = mLoN; mHi = mHiN;
    }

    // reduce across the 4 lanes (tg) sharing each row
    float c0f = (float)C0, c1f = (float)C1;
#pragma unroll
    for (int o = 2; o > 0; o >>= 1) {
        T0 += __shfl_down_sync(0xffffffffu, T0, o, 4);
        A0 += __shfl_down_sync(0xffffffffu, A0, o, 4);
        P0 += __shfl_down_sync(0xffffffffu, P0, o, 4);
        c0f += __shfl_down_sync(0xffffffffu, c0f, o, 4);
        T1 += __shfl_down_sync(0xffffffffu, T1, o, 4);
        A1 += __shfl_down_sync(0xffffffffu, A1, o, 4);
        P1 += __shfl_down_sync(0xffffffffu, P1, o, 4);
        c1f += __shfl_down_sync(0xffffffffu, c1f, o, 4);
    }
    if (tg == 0) {
        sRow[(size_t)(rg * 16 + g) * 8 + q]     = make_float4(T0, A0, P0, c0f);
        sRow[(size_t)(rg * 16 + g + 8) * 8 + q] = make_float4(T1, A1, P1, c1f);
    }
    __syncthreads();

    // ---------------- Phase C: per-row closed form (warp 0) -----------------
    if (tid < 32) {
        const int row = tid;
        const int i   = i0 + row;
        float4 s = make_float4(0.f, 0.f, 0.f, 0.f);
#pragma unroll
        for (int qq = 0; qq < 8; qq++) {
            float4 v = sRow[(size_t)row * 8 + qq];
            s.x += v.x; s.y += v.y; s.z += v.z; s.w += v.w;
        }
        // Taylor-3-consistent e^{sigmoid(5)} (matches in-loop diag element)
        const float EXDIAG_T = 2.6499793f;
        float md = (mask[((size_t)(b * NN + i)) * NN + i] != 0) ? 1.f : 0.f;
        float S  = s.x - s.y - (1.f - md) * EXDIAG_T;
        float L  = __logf(S);
        float contrib = s.w * L - s.z + s.y * __fdividef(1.f, S);
#pragma unroll
        for (int o = 16; o > 0; o >>= 1)
            contrib += __shfl_down_sync(0xffffffffu, contrib, o);
        if (tid == 0) {
            g_part[b * 32 + blockIdx.x] = contrib;
            __threadfence();
            unsigned v = atomicAdd(&g_done, 1u);
            sIsLast = (v == 127u);
        }
    }
    __syncthreads();

    // Last CTA: deterministic fixed-order tree over the 128 partials
    if (sIsLast) {
        double* dsh = reinterpret_cast<double*>(smem);
        if (tid < 128) dsh[tid] = (double)g_part[tid];
        __syncthreads();
#pragma unroll
        for (int s = 64; s > 0; s >>= 1) {
            if (tid < s) dsh[tid] += dsh[tid + s];
            __syncthreads();
        }
        if (tid == 0) {
            out[0] = (float)dsh[0];
            g_done = 0;                 // reset for next replay
        }
    }
}

// ---------------------------------------------------------------------------
extern "C" void kernel_launch(void* const* d_in, const int* in_sizes, int n_in,
                              void* d_out, int out_size) {
    (void)in_sizes; (void)n_in; (void)out_size;
    const float* emb    = (const float*)d_in[0];   // [4,1024,32]
    const float* coords = (const float*)d_in[1];   // [4,1024,2]
    const int*   mask   = (const int*)d_in[2];     // [4,1024,1024] bool->int32
    float* out          = (float*)d_out;           // scalar

    size_t smem = (size_t)NN * RSTRIDE              // sB    81920
                + (size_t)NN * sizeof(float)        // sN     4096
                + (size_t)32 * 8 * sizeof(float4);  // sRow   4096
    cudaFuncSetAttribute(fused_kernel, cudaFuncAttributeMaxDynamicSharedMemorySize,
                         (int)smem);
    fused_kernel<<<dim3(32, 4), 512, smem>>>(emb, coords, mask, out);
}